// round 7
// baseline (speedup 1.0000x reference)
#include <cuda_runtime.h>
#include <cuda_bf16.h>
#include <math.h>
#include <stdint.h>

#define N_ROWS 4096
#define D_DIM  1024
#define TWO_N  8192
#define NEG_INF (-1e30f)

// fp8 inputs are pre-scaled by 32 -> products carry 1024x; fold into temp scale
#define INV_TEMP_EFF (20.0f / 1024.0f)
#define QSCALE 32.0f

#define BM 128
#define BN 128
#define BK 64                    // fp8 elements per k-chunk (64 bytes/row)
#define NK (D_DIM / BK)          // 16 k-chunks
#define CT_TILES (TWO_N / BN)    // 64 column tiles
#define RB_TILES (N_ROWS / BM)   // 32 row tiles
#define PCOLS (CT_TILES * 4)     // 256 partials per row
#define NSTAGE 3
#define SBUF_BYTES (128 * 64)    // 8 KB: 128 rows x 64 B, XOR swizzled

// XOR swizzle: row r (0..127), 16B chunk c (0..3) -> byte offset.
// Conflict-free for cp.async 16B stores and all ldmatrix phases.
#define SWOFF(r, c) (((uint32_t)(r) << 6) | ((((c) ^ (((r) >> 1) & 3))) << 4))

// -------------------------- scratch (no allocs) ----------------------------
__device__ uint8_t g_Xn[(size_t)N_ROWS * D_DIM];         // 4 MB  e4m3
__device__ uint8_t g_Bn[(size_t)TWO_N * D_DIM];          // 8 MB  e4m3 (tgt ; neg)
__device__ float g_diag[N_ROWS];
__device__ float g_pm[(size_t)N_ROWS * PCOLS];           // 4 MB
__device__ float g_ps[(size_t)N_ROWS * PCOLS];           // 4 MB
__device__ float g_bsum[16];

// -------------------------- PTX helpers ------------------------------------
__device__ __forceinline__ uint32_t smem_u32(const void* p) {
    uint32_t a;
    asm("{ .reg .u64 t; cvta.to.shared.u64 t, %1; cvt.u32.u64 %0, t; }" : "=r"(a) : "l"(p));
    return a;
}

#define CP_ASYNC16(saddr, gptr) \
    asm volatile("cp.async.cg.shared.global [%0], [%1], 16;" :: "r"(saddr), "l"(gptr))
#define CP_COMMIT() asm volatile("cp.async.commit_group;" ::: "memory")
#define CP_WAIT1()  asm volatile("cp.async.wait_group 1;" ::: "memory")

#define LDSM_X4(r, a) \
    asm volatile("ldmatrix.sync.aligned.m8n8.x4.shared.b16 {%0,%1,%2,%3}, [%4];" \
        : "=r"((r)[0]), "=r"((r)[1]), "=r"((r)[2]), "=r"((r)[3]) : "r"(a))
#define LDSM_X2(r, a) \
    asm volatile("ldmatrix.sync.aligned.m8n8.x2.shared.b16 {%0,%1}, [%2];" \
        : "=r"((r)[0]), "=r"((r)[1]) : "r"(a))

// fp8 e4m3 MMA: m16n8k32, fragments are layout-isomorphic to bf16 m16n8k16
// with each b16 element = 2 fp8 along K (so b16 ldmatrix loads work unchanged).
#define MMA16832(d, a, b) \
    asm volatile("mma.sync.aligned.m16n8k32.row.col.f32.e4m3.e4m3.f32 " \
        "{%0,%1,%2,%3}, {%4,%5,%6,%7}, {%8,%9}, {%0,%1,%2,%3};" \
        : "+f"((d)[0]), "+f"((d)[1]), "+f"((d)[2]), "+f"((d)[3]) \
        : "r"((a)[0]), "r"((a)[1]), "r"((a)[2]), "r"((a)[3]), "r"((b)[0]), "r"((b)[1]))

__device__ __forceinline__ uint32_t pack_e4m3x4(float x0, float x1, float x2, float x3) {
    uint16_t lo, hi;
    asm("cvt.rn.satfinite.e4m3x2.f32 %0, %1, %2;" : "=h"(lo) : "f"(x1), "f"(x0));
    asm("cvt.rn.satfinite.e4m3x2.f32 %0, %1, %2;" : "=h"(hi) : "f"(x3), "f"(x2));
    return (uint32_t)lo | ((uint32_t)hi << 16);
}

// ---------------------------------------------------------------------------
// Kernel 1: row-normalize -> e4m3 (x32 prescale), warp-per-row.
// target -> g_Bn[0:N), hard_neg -> g_Bn[N:2N)
// ---------------------------------------------------------------------------
__global__ __launch_bounds__(256) void normalize_kernel(
    const float* __restrict__ inp,
    const float* __restrict__ tgt,
    const float* __restrict__ neg)
{
    const int wid  = threadIdx.x >> 5;
    const int lane = threadIdx.x & 31;
    const int row  = blockIdx.x * 8 + wid;     // 0..12287

    const float* src;
    uint8_t* dst;
    if (row < N_ROWS) {
        src = inp + (size_t)row * D_DIM;
        dst = g_Xn + (size_t)row * D_DIM;
    } else if (row < 2 * N_ROWS) {
        int r = row - N_ROWS;
        src = tgt + (size_t)r * D_DIM;
        dst = g_Bn + (size_t)r * D_DIM;
    } else {
        int r = row - 2 * N_ROWS;
        src = neg + (size_t)r * D_DIM;
        dst = g_Bn + (size_t)(N_ROWS + r) * D_DIM;
    }

    float4 v[8];
    float ss = 0.f;
    #pragma unroll
    for (int i = 0; i < 8; i++) {
        v[i] = ((const float4*)src)[lane + 32 * i];
        ss += v[i].x * v[i].x + v[i].y * v[i].y + v[i].z * v[i].z + v[i].w * v[i].w;
    }
    #pragma unroll
    for (int o = 16; o; o >>= 1) ss += __shfl_xor_sync(0xffffffffu, ss, o);
    const float inv = QSCALE / fmaxf(sqrtf(ss), 1e-8f);

    #pragma unroll
    for (int i = 0; i < 8; i++) {
        uint32_t p = pack_e4m3x4(v[i].x * inv, v[i].y * inv, v[i].z * inv, v[i].w * inv);
        ((uint32_t*)dst)[lane + 32 * i] = p;
    }
}

// ---------------------------------------------------------------------------
// Kernel 2: fp8 HMMA GEMM (mma.sync m16n8k32) + fused online logsumexp.
// 128x128 tile per CTA, 8 warps (2x4), 3-stage cp.async pipeline,
// XOR-swizzled 64B-row smem (48 KB total, conflict-free).
// ---------------------------------------------------------------------------
__global__ __launch_bounds__(256) void sim_lse_mma()
{
    __shared__ alignas(1024) uint8_t sA[NSTAGE][128 * 64];
    __shared__ alignas(1024) uint8_t sB[NSTAGE][128 * 64];

    const int tid    = threadIdx.x;
    const int wid    = tid >> 5;
    const int lane   = tid & 31;
    const int warp_m = wid >> 2;        // 0..1
    const int warp_n = wid & 3;         // 0..3
    const int ct     = blockIdx.x;      // 0..63
    const int rb     = blockIdx.y;      // 0..31
    const int row0   = rb * BM;
    const int col0   = ct * BN;

    const uint32_t aA = smem_u32(sA);
    const uint32_t aB = smem_u32(sB);

    // cp.async: thread handles segments tid and tid+256 (row = seg>>2, chunk = seg&3)
    const int ldr0 = tid >> 2;
    const int ldc0 = tid & 3;
    const int ldr1 = (tid + 256) >> 2;
    const int ldc1 = (tid + 256) & 3;
    const uint32_t d0 = SWOFF(ldr0, ldc0);
    const uint32_t d1 = SWOFF(ldr1, ldc1);
    const uint8_t* gA0 = &g_Xn[(size_t)(row0 + ldr0) * D_DIM + ldc0 * 16];
    const uint8_t* gA1 = &g_Xn[(size_t)(row0 + ldr1) * D_DIM + ldc1 * 16];
    const uint8_t* gB0 = &g_Bn[(size_t)(col0 + ldr0) * D_DIM + ldc0 * 16];
    const uint8_t* gB1 = &g_Bn[(size_t)(col0 + ldr1) * D_DIM + ldc1 * 16];

    // Precomputed ldmatrix lane offsets (within one stage buffer).
    // ks selects 32 fp8 (= 2 x 16B chunks) of the 64B row.
    uint32_t a_off[4][2], b_off[4][2];
    #pragma unroll
    for (int mt = 0; mt < 4; mt++) {
        const int r = warp_m * 64 + mt * 16 + (lane & 15);
        const int cb = lane >> 4;
        #pragma unroll
        for (int ks = 0; ks < 2; ks++) a_off[mt][ks] = SWOFF(r, ks * 2 + cb);
    }
    #pragma unroll
    for (int nt = 0; nt < 4; nt++) {
        const int r = warp_n * 32 + nt * 8 + (lane & 7);
        const int cb = (lane >> 3) & 1;
        #pragma unroll
        for (int ks = 0; ks < 2; ks++) b_off[nt][ks] = SWOFF(r, ks * 2 + cb);
    }

    float acc[4][4][4];
    #pragma unroll
    for (int mt = 0; mt < 4; mt++)
        #pragma unroll
        for (int nt = 0; nt < 4; nt++)
            #pragma unroll
            for (int q = 0; q < 4; q++) acc[mt][nt][q] = 0.f;

    // prologue: stages 0 and 1
    #pragma unroll
    for (int p = 0; p < 2; p++) {
        const int k0 = p * BK;
        const uint32_t dA = aA + p * SBUF_BYTES;
        const uint32_t dB = aB + p * SBUF_BYTES;
        CP_ASYNC16(dA + d0, gA0 + k0);
        CP_ASYNC16(dB + d0, gB0 + k0);
        CP_ASYNC16(dA + d1, gA1 + k0);
        CP_ASYNC16(dB + d1, gB1 + k0);
        CP_COMMIT();
    }

    int stage = 0;
    for (int kc = 0; kc < NK; kc++) {
        CP_WAIT1();
        __syncthreads();

        if (kc + 2 < NK) {
            const int ps = (stage + 2 >= NSTAGE) ? stage + 2 - NSTAGE : stage + 2;
            const int k0 = (kc + 2) * BK;
            const uint32_t dA = aA + ps * SBUF_BYTES;
            const uint32_t dB = aB + ps * SBUF_BYTES;
            CP_ASYNC16(dA + d0, gA0 + k0);
            CP_ASYNC16(dB + d0, gB0 + k0);
            CP_ASYNC16(dA + d1, gA1 + k0);
            CP_ASYNC16(dB + d1, gB1 + k0);
        }
        CP_COMMIT();

        const uint32_t baseA = aA + stage * SBUF_BYTES;
        const uint32_t baseB = aB + stage * SBUF_BYTES;
        #pragma unroll
        for (int ks = 0; ks < 2; ks++) {
            uint32_t af[4][4], bf[4][2];
            #pragma unroll
            for (int mt = 0; mt < 4; mt++) LDSM_X4(af[mt], baseA + a_off[mt][ks]);
            #pragma unroll
            for (int nt = 0; nt < 4; nt++) LDSM_X2(bf[nt], baseB + b_off[nt][ks]);
            #pragma unroll
            for (int mt = 0; mt < 4; mt++)
                #pragma unroll
                for (int nt = 0; nt < 4; nt++)
                    MMA16832(acc[mt][nt], af[mt], bf[nt]);
        }
        stage = (stage + 1 >= NSTAGE) ? 0 : stage + 1;
    }

    // ---- Epilogue: per-row online LSE over this warp's 32 columns ----
    #pragma unroll
    for (int mt = 0; mt < 4; mt++) {
        #pragma unroll
        for (int h = 0; h < 2; h++) {
            const int gr = row0 + warp_m * 64 + mt * 16 + (lane >> 2) + h * 8;
            float v[8];
            float m = NEG_INF;
            #pragma unroll
            for (int nt = 0; nt < 4; nt++) {
                #pragma unroll
                for (int j = 0; j < 2; j++) {
                    float x = acc[mt][nt][h * 2 + j] * INV_TEMP_EFF;
                    const int gc = col0 + warp_n * 32 + nt * 8 + (lane & 3) * 2 + j;
                    if (gc == gr) g_diag[gr] = x;           // pos_sim diagonal
                    if (gc == N_ROWS + gr) x += 1.0f;       // hard-negative weight
                    v[nt * 2 + j] = x;
                    m = fmaxf(m, x);
                }
            }
            float s = 0.f;
            #pragma unroll
            for (int j = 0; j < 8; j++) s += __expf(v[j] - m);
            #pragma unroll
            for (int off = 1; off <= 2; off <<= 1) {
                float om = __shfl_xor_sync(0xffffffffu, m, off);
                float os = __shfl_xor_sync(0xffffffffu, s, off);
                float mn = fmaxf(m, om);
                s = s * __expf(m - mn) + os * __expf(om - mn);
                m = mn;
            }
            if ((lane & 3) == 0) {
                const size_t p = (size_t)gr * PCOLS + ct * 4 + warp_n;
                g_pm[p] = m;
                g_ps[p] = s;
            }
        }
    }
}

// ---------------------------------------------------------------------------
// Kernel 3a: per-row combine (256 partials) -> lse - diag; block partial sum.
// ---------------------------------------------------------------------------
__global__ __launch_bounds__(256) void rowloss_kernel()
{
    const int tid = threadIdx.x;
    const int r = blockIdx.x * 256 + tid;
    const float* pm = &g_pm[(size_t)r * PCOLS];
    const float* ps = &g_ps[(size_t)r * PCOLS];
    float m = NEG_INF;
    #pragma unroll 8
    for (int c = 0; c < PCOLS; c++) m = fmaxf(m, pm[c]);
    float s = 0.f;
    #pragma unroll 8
    for (int c = 0; c < PCOLS; c++) s += ps[c] * __expf(pm[c] - m);
    float local = (m + logf(s)) - g_diag[r];

    #pragma unroll
    for (int o = 16; o; o >>= 1) local += __shfl_xor_sync(0xffffffffu, local, o);
    __shared__ float warp_sum[8];
    const int w = tid >> 5, l = tid & 31;
    if (l == 0) warp_sum[w] = local;
    __syncthreads();
    if (tid == 0) {
        float t = 0.f;
        #pragma unroll
        for (int i = 0; i < 8; i++) t += warp_sum[i];
        g_bsum[blockIdx.x] = t;
    }
}

// ---------------------------------------------------------------------------
// Kernel 3b: one warp sums the 16 block partials.
// ---------------------------------------------------------------------------
__global__ __launch_bounds__(32) void finalize_kernel(float* __restrict__ out)
{
    const int lane = threadIdx.x;
    float v = (lane < 16) ? g_bsum[lane] : 0.f;
    #pragma unroll
    for (int o = 16; o; o >>= 1) v += __shfl_xor_sync(0xffffffffu, v, o);
    if (lane == 0) out[0] = v / (float)N_ROWS;
}

// ---------------------------------------------------------------------------
extern "C" void kernel_launch(void* const* d_in, const int* in_sizes, int n_in,
                              void* d_out, int out_size)
{
    const float* inp = (const float*)d_in[0];
    const float* tgt = (const float*)d_in[1];
    const float* neg = (const float*)d_in[2];
    float* out = (float*)d_out;

    normalize_kernel<<<(3 * N_ROWS) / 8, 256>>>(inp, tgt, neg);

    dim3 grid(CT_TILES, RB_TILES);   // 64 x 32 = 2048 CTAs
    sim_lse_mma<<<grid, 256>>>();

    rowloss_kernel<<<N_ROWS / 256, 256>>>();
    finalize_kernel<<<1, 32>>>(out);
}

// round 8
// speedup vs baseline: 1.2438x; 1.2438x over previous
#include <cuda_runtime.h>
#include <cuda_bf16.h>
#include <math.h>
#include <stdint.h>

#define N_ROWS 4096
#define D_DIM  1024
#define TWO_N  8192
#define INV_TEMP 20.0f
#define NEG_INF (-1e30f)

#define BM 128
#define BN 128
#define BK 64                    // bf16 elements per k-chunk (128 B rows)
#define NK (D_DIM / BK)          // 16 k-chunks
#define CT_TILES (TWO_N / BN)    // 64 column tiles
#define RB_TILES (N_ROWS / BM)   // 32 row tiles
#define PCOLS (CT_TILES * 4)     // 256 partials per row
#define NSTAGE 3
#define STAGE_BYTES (2 * 128 * 128)      // sA (16 KB) + sB (16 KB) per stage
#define SMEM_TOTAL (NSTAGE * STAGE_BYTES) // 96 KB dynamic

// Full-width XOR swizzle for 128B rows: row r (0..127), 16B chunk c (0..7).
// chunk' = c ^ (r & 7): conflict-free for cp.async 16B stores (permutation
// within each row) and every ldmatrix phase (8 consecutive rows -> 8 distinct
// 16B banks mod 128B).
#define SWOFF128(r, c) (((uint32_t)(r) << 7) | ((((c) ^ ((r) & 7))) << 4))

// -------------------------- scratch (no allocs) ----------------------------
__device__ __nv_bfloat16 g_Xn[(size_t)N_ROWS * D_DIM];   // 8 MB
__device__ __nv_bfloat16 g_Bn[(size_t)TWO_N * D_DIM];    // 16 MB (tgt ; neg)
__device__ float g_diag[N_ROWS];
__device__ float g_pm[(size_t)N_ROWS * PCOLS];           // 4 MB
__device__ float g_ps[(size_t)N_ROWS * PCOLS];           // 4 MB
__device__ float g_bsum[16];

// -------------------------- PTX helpers ------------------------------------
__device__ __forceinline__ uint32_t smem_u32(const void* p) {
    uint32_t a;
    asm("{ .reg .u64 t; cvta.to.shared.u64 t, %1; cvt.u32.u64 %0, t; }" : "=r"(a) : "l"(p));
    return a;
}

#define CP_ASYNC16(saddr, gptr) \
    asm volatile("cp.async.cg.shared.global [%0], [%1], 16;" :: "r"(saddr), "l"(gptr))
#define CP_COMMIT() asm volatile("cp.async.commit_group;" ::: "memory")
#define CP_WAIT1()  asm volatile("cp.async.wait_group 1;" ::: "memory")

#define LDSM_X4(r, a) \
    asm volatile("ldmatrix.sync.aligned.m8n8.x4.shared.b16 {%0,%1,%2,%3}, [%4];" \
        : "=r"((r)[0]), "=r"((r)[1]), "=r"((r)[2]), "=r"((r)[3]) : "r"(a))
#define LDSM_X2(r, a) \
    asm volatile("ldmatrix.sync.aligned.m8n8.x2.shared.b16 {%0,%1}, [%2];" \
        : "=r"((r)[0]), "=r"((r)[1]) : "r"(a))

#define MMA16816(d, a, b) \
    asm volatile("mma.sync.aligned.m16n8k16.row.col.f32.bf16.bf16.f32 " \
        "{%0,%1,%2,%3}, {%4,%5,%6,%7}, {%8,%9}, {%0,%1,%2,%3};" \
        : "+f"((d)[0]), "+f"((d)[1]), "+f"((d)[2]), "+f"((d)[3]) \
        : "r"((a)[0]), "r"((a)[1]), "r"((a)[2]), "r"((a)[3]), "r"((b)[0]), "r"((b)[1]))

// ---------------------------------------------------------------------------
// Kernel 1: row-normalize -> bf16, warp-per-row (no block sync).
// target -> g_Bn[0:N), hard_neg -> g_Bn[N:2N)
// ---------------------------------------------------------------------------
__global__ __launch_bounds__(256) void normalize_kernel(
    const float* __restrict__ inp,
    const float* __restrict__ tgt,
    const float* __restrict__ neg)
{
    const int wid  = threadIdx.x >> 5;
    const int lane = threadIdx.x & 31;
    const int row  = blockIdx.x * 8 + wid;     // 0..12287

    const float* src;
    __nv_bfloat16* dst;
    if (row < N_ROWS) {
        src = inp + (size_t)row * D_DIM;
        dst = g_Xn + (size_t)row * D_DIM;
    } else if (row < 2 * N_ROWS) {
        int r = row - N_ROWS;
        src = tgt + (size_t)r * D_DIM;
        dst = g_Bn + (size_t)r * D_DIM;
    } else {
        int r = row - 2 * N_ROWS;
        src = neg + (size_t)r * D_DIM;
        dst = g_Bn + (size_t)(N_ROWS + r) * D_DIM;
    }

    float4 v[8];
    float ss = 0.f;
    #pragma unroll
    for (int i = 0; i < 8; i++) {
        v[i] = ((const float4*)src)[lane + 32 * i];
        ss += v[i].x * v[i].x + v[i].y * v[i].y + v[i].z * v[i].z + v[i].w * v[i].w;
    }
    #pragma unroll
    for (int o = 16; o; o >>= 1) ss += __shfl_xor_sync(0xffffffffu, ss, o);
    const float inv = 1.0f / fmaxf(sqrtf(ss), 1e-8f);

    #pragma unroll
    for (int i = 0; i < 8; i++) {
        __nv_bfloat162 h0 = __floats2bfloat162_rn(v[i].x * inv, v[i].y * inv);
        __nv_bfloat162 h1 = __floats2bfloat162_rn(v[i].z * inv, v[i].w * inv);
        uint2 packed;
        packed.x = *(uint32_t*)&h0;
        packed.y = *(uint32_t*)&h1;
        ((uint2*)dst)[lane + 32 * i] = packed;
    }
}

// ---------------------------------------------------------------------------
// Kernel 2: bf16 HMMA GEMM (mma.sync m16n8k16) + fused online logsumexp.
// 128x128 tile per CTA, 8 warps (2x4), BK=64 (16 syncs instead of 32),
// 3-stage cp.async pipeline in 96 KB dynamic smem, XOR-swizzled 128B rows.
// ---------------------------------------------------------------------------
__global__ __launch_bounds__(256, 2) void sim_lse_mma()
{
    extern __shared__ __align__(1024) uint8_t smem_dyn[];

    const int tid    = threadIdx.x;
    const int wid    = tid >> 5;
    const int lane   = tid & 31;
    const int warp_m = wid >> 2;        // 0..1
    const int warp_n = wid & 3;         // 0..3
    const int ct     = blockIdx.x;      // 0..63
    const int rb     = blockIdx.y;      // 0..31
    const int row0   = rb * BM;
    const int col0   = ct * BN;

    const uint32_t sbase = smem_u32(smem_dyn);

    // cp.async: 4 segments per matrix per chunk per thread.
    // seg = tid + i*256 -> row = seg>>3, 16B-chunk = seg&7.
    uint32_t doff[4];
    const __nv_bfloat16* gA[4];
    const __nv_bfloat16* gB[4];
    #pragma unroll
    for (int i = 0; i < 4; i++) {
        const int seg = tid + i * 256;
        const int r = seg >> 3;
        const int c = seg & 7;
        doff[i] = SWOFF128(r, c);
        gA[i] = &g_Xn[(size_t)(row0 + r) * D_DIM + c * 8];
        gB[i] = &g_Bn[(size_t)(col0 + r) * D_DIM + c * 8];
    }

    // ldmatrix row bases (chunk index folded in at use; xr = row&7 for swizzle)
    uint32_t a_row[4], b_row[4];
    uint32_t a_xr[4], b_xr[4];
    const uint32_t a_cb = lane >> 4;          // 0..1
    const uint32_t b_cb = (lane >> 3) & 1;    // 0..1
    #pragma unroll
    for (int mt = 0; mt < 4; mt++) {
        const int r = warp_m * 64 + mt * 16 + (lane & 15);
        a_row[mt] = (uint32_t)r << 7;
        a_xr[mt]  = (uint32_t)(r & 7);
    }
    #pragma unroll
    for (int nt = 0; nt < 4; nt++) {
        const int r = warp_n * 32 + nt * 8 + (lane & 7);
        b_row[nt] = (uint32_t)r << 7;
        b_xr[nt]  = (uint32_t)(r & 7);
    }

    float acc[4][4][4];
    #pragma unroll
    for (int mt = 0; mt < 4; mt++)
        #pragma unroll
        for (int nt = 0; nt < 4; nt++)
            #pragma unroll
            for (int q = 0; q < 4; q++) acc[mt][nt][q] = 0.f;

    // prologue: stages 0 and 1 (chunks 0 and 1)
    #pragma unroll
    for (int p = 0; p < 2; p++) {
        const int k0 = p * BK;
        const uint32_t dA = sbase + p * STAGE_BYTES;
        const uint32_t dB = dA + 128 * 128;
        #pragma unroll
        for (int i = 0; i < 4; i++) {
            CP_ASYNC16(dA + doff[i], gA[i] + k0);
            CP_ASYNC16(dB + doff[i], gB[i] + k0);
        }
        CP_COMMIT();
    }

    int stage = 0;
    for (int kc = 0; kc < NK; kc++) {
        CP_WAIT1();
        __syncthreads();

        if (kc + 2 < NK) {
            const int ps = (stage + 2 >= NSTAGE) ? stage + 2 - NSTAGE : stage + 2;
            const int k0 = (kc + 2) * BK;
            const uint32_t dA = sbase + ps * STAGE_BYTES;
            const uint32_t dB = dA + 128 * 128;
            #pragma unroll
            for (int i = 0; i < 4; i++) {
                CP_ASYNC16(dA + doff[i], gA[i] + k0);
                CP_ASYNC16(dB + doff[i], gB[i] + k0);
            }
        }
        CP_COMMIT();

        const uint32_t baseA = sbase + stage * STAGE_BYTES;
        const uint32_t baseB = baseA + 128 * 128;
        #pragma unroll
        for (int ks = 0; ks < 4; ks++) {
            uint32_t af[4][4], bf[4][2];
            #pragma unroll
            for (int mt = 0; mt < 4; mt++) {
                const uint32_t chunk = (2u * ks + a_cb) ^ a_xr[mt];
                LDSM_X4(af[mt], baseA + (a_row[mt] | (chunk << 4)));
            }
            #pragma unroll
            for (int nt = 0; nt < 4; nt++) {
                const uint32_t chunk = (2u * ks + b_cb) ^ b_xr[nt];
                LDSM_X2(bf[nt], baseB + (b_row[nt] | (chunk << 4)));
            }
            #pragma unroll
            for (int mt = 0; mt < 4; mt++)
                #pragma unroll
                for (int nt = 0; nt < 4; nt++)
                    MMA16816(acc[mt][nt], af[mt], bf[nt]);
        }
        stage = (stage + 1 >= NSTAGE) ? 0 : stage + 1;
    }

    // ---- Epilogue: per-row online LSE over this warp's 32 columns ----
    #pragma unroll
    for (int mt = 0; mt < 4; mt++) {
        #pragma unroll
        for (int h = 0; h < 2; h++) {
            const int gr = row0 + warp_m * 64 + mt * 16 + (lane >> 2) + h * 8;
            float v[8];
            float m = NEG_INF;
            #pragma unroll
            for (int nt = 0; nt < 4; nt++) {
                #pragma unroll
                for (int j = 0; j < 2; j++) {
                    float x = acc[mt][nt][h * 2 + j] * INV_TEMP;
                    const int gc = col0 + warp_n * 32 + nt * 8 + (lane & 3) * 2 + j;
                    if (gc == gr) g_diag[gr] = x;           // pos_sim diagonal
                    if (gc == N_ROWS + gr) x += 1.0f;       // hard-negative weight
                    v[nt * 2 + j] = x;
                    m = fmaxf(m, x);
                }
            }
            float s = 0.f;
            #pragma unroll
            for (int j = 0; j < 8; j++) s += __expf(v[j] - m);
            #pragma unroll
            for (int off = 1; off <= 2; off <<= 1) {
                float om = __shfl_xor_sync(0xffffffffu, m, off);
                float os = __shfl_xor_sync(0xffffffffu, s, off);
                float mn = fmaxf(m, om);
                s = s * __expf(m - mn) + os * __expf(om - mn);
                m = mn;
            }
            if ((lane & 3) == 0) {
                const size_t p = (size_t)gr * PCOLS + ct * 4 + warp_n;
                g_pm[p] = m;
                g_ps[p] = s;
            }
        }
    }
}

// ---------------------------------------------------------------------------
// Kernel 3a: per-row combine (256 partials) -> lse - diag; block partial sum.
// ---------------------------------------------------------------------------
__global__ __launch_bounds__(256) void rowloss_kernel()
{
    const int tid = threadIdx.x;
    const int r = blockIdx.x * 256 + tid;
    const float* pm = &g_pm[(size_t)r * PCOLS];
    const float* ps = &g_ps[(size_t)r * PCOLS];
    float m = NEG_INF;
    #pragma unroll 8
    for (int c = 0; c < PCOLS; c++) m = fmaxf(m, pm[c]);
    float s = 0.f;
    #pragma unroll 8
    for (int c = 0; c < PCOLS; c++) s += ps[c] * __expf(pm[c] - m);
    float local = (m + logf(s)) - g_diag[r];

    #pragma unroll
    for (int o = 16; o; o >>= 1) local += __shfl_xor_sync(0xffffffffu, local, o);
    __shared__ float warp_sum[8];
    const int w = tid >> 5, l = tid & 31;
    if (l == 0) warp_sum[w] = local;
    __syncthreads();
    if (tid == 0) {
        float t = 0.f;
        #pragma unroll
        for (int i = 0; i < 8; i++) t += warp_sum[i];
        g_bsum[blockIdx.x] = t;
    }
}

// ---------------------------------------------------------------------------
// Kernel 3b: one warp sums the 16 block partials.
// ---------------------------------------------------------------------------
__global__ __launch_bounds__(32) void finalize_kernel(float* __restrict__ out)
{
    const int lane = threadIdx.x;
    float v = (lane < 16) ? g_bsum[lane] : 0.f;
    #pragma unroll
    for (int o = 16; o; o >>= 1) v += __shfl_xor_sync(0xffffffffu, v, o);
    if (lane == 0) out[0] = v / (float)N_ROWS;
}

// ---------------------------------------------------------------------------
extern "C" void kernel_launch(void* const* d_in, const int* in_sizes, int n_in,
                              void* d_out, int out_size)
{
    const float* inp = (const float*)d_in[0];
    const float* tgt = (const float*)d_in[1];
    const float* neg = (const float*)d_in[2];
    float* out = (float*)d_out;

    // Opt-in to 96 KB dynamic smem (host-side attribute set; capture-legal).
    cudaFuncSetAttribute(sim_lse_mma,
                         cudaFuncAttributeMaxDynamicSharedMemorySize, SMEM_TOTAL);

    normalize_kernel<<<(3 * N_ROWS) / 8, 256>>>(inp, tgt, neg);

    dim3 grid(CT_TILES, RB_TILES);   // 64 x 32 = 2048 CTAs
    sim_lse_mma<<<grid, 256, SMEM_TOTAL>>>();

    rowloss_kernel<<<N_ROWS / 256, 256>>>();
    finalize_kernel<<<1, 32>>>(out);
}

// round 9
// speedup vs baseline: 1.8795x; 1.5111x over previous
#include <cuda_runtime.h>
#include <cuda_bf16.h>
#include <math.h>
#include <stdint.h>

#define N_ROWS 4096
#define D_DIM  1024
#define TWO_N  8192
#define INV_TEMP 20.0f
#define NEG_INF (-1e30f)

#define BM 128
#define BN 128
#define BK 64                    // bf16 elements per k-chunk (128 B rows)
#define NK (D_DIM / BK)          // 16 k-chunks
#define CT_TILES (TWO_N / BN)    // 64 column tiles
#define RB_TILES (N_ROWS / BM)   // 32 row tiles
#define NSTAGE 3
#define STAGE_BYTES (2 * 128 * 128)      // sA (16 KB) + sB (16 KB) per stage
#define SMEM_TOTAL (NSTAGE * STAGE_BYTES) // 96 KB dynamic

// Full-width XOR swizzle for 128B rows: row r (0..127), 16B chunk c (0..7).
// chunk' = c ^ (r & 7): conflict-free for cp.async 16B stores and every
// ldmatrix phase.
#define SWOFF128(r, c) (((uint32_t)(r) << 7) | ((((c) ^ ((r) & 7))) << 4))

// -------------------------- scratch (no allocs) ----------------------------
__device__ __nv_bfloat16 g_Xn[(size_t)N_ROWS * D_DIM];   // 8 MB
__device__ __nv_bfloat16 g_Bn[(size_t)TWO_N * D_DIM];    // 16 MB (tgt ; neg)
__device__ float g_diag[N_ROWS];
// ct-major partials: g_pm[ct * N_ROWS + row]  (1 MB each)
__device__ float g_pm[(size_t)CT_TILES * N_ROWS];
__device__ float g_ps[(size_t)CT_TILES * N_ROWS];
__device__ float g_bsum[16];

// -------------------------- PTX helpers ------------------------------------
__device__ __forceinline__ uint32_t smem_u32(const void* p) {
    uint32_t a;
    asm("{ .reg .u64 t; cvta.to.shared.u64 t, %1; cvt.u32.u64 %0, t; }" : "=r"(a) : "l"(p));
    return a;
}

#define CP_ASYNC16(saddr, gptr) \
    asm volatile("cp.async.cg.shared.global [%0], [%1], 16;" :: "r"(saddr), "l"(gptr))
#define CP_COMMIT() asm volatile("cp.async.commit_group;" ::: "memory")
#define CP_WAIT1()  asm volatile("cp.async.wait_group 1;" ::: "memory")

#define LDSM_X4(r, a) \
    asm volatile("ldmatrix.sync.aligned.m8n8.x4.shared.b16 {%0,%1,%2,%3}, [%4];" \
        : "=r"((r)[0]), "=r"((r)[1]), "=r"((r)[2]), "=r"((r)[3]) : "r"(a))
#define LDSM_X2(r, a) \
    asm volatile("ldmatrix.sync.aligned.m8n8.x2.shared.b16 {%0,%1}, [%2];" \
        : "=r"((r)[0]), "=r"((r)[1]) : "r"(a))

#define MMA16816(d, a, b) \
    asm volatile("mma.sync.aligned.m16n8k16.row.col.f32.bf16.bf16.f32 " \
        "{%0,%1,%2,%3}, {%4,%5,%6,%7}, {%8,%9}, {%0,%1,%2,%3};" \
        : "+f"((d)[0]), "+f"((d)[1]), "+f"((d)[2]), "+f"((d)[3]) \
        : "r"((a)[0]), "r"((a)[1]), "r"((a)[2]), "r"((a)[3]), "r"((b)[0]), "r"((b)[1]))

// ---------------------------------------------------------------------------
// Kernel 1: row-normalize -> bf16, warp-per-row (no block sync).
// target -> g_Bn[0:N), hard_neg -> g_Bn[N:2N)
// ---------------------------------------------------------------------------
__global__ __launch_bounds__(256) void normalize_kernel(
    const float* __restrict__ inp,
    const float* __restrict__ tgt,
    const float* __restrict__ neg)
{
    const int wid  = threadIdx.x >> 5;
    const int lane = threadIdx.x & 31;
    const int row  = blockIdx.x * 8 + wid;     // 0..12287

    const float* src;
    __nv_bfloat16* dst;
    if (row < N_ROWS) {
        src = inp + (size_t)row * D_DIM;
        dst = g_Xn + (size_t)row * D_DIM;
    } else if (row < 2 * N_ROWS) {
        int r = row - N_ROWS;
        src = tgt + (size_t)r * D_DIM;
        dst = g_Bn + (size_t)r * D_DIM;
    } else {
        int r = row - 2 * N_ROWS;
        src = neg + (size_t)r * D_DIM;
        dst = g_Bn + (size_t)(N_ROWS + r) * D_DIM;
    }

    float4 v[8];
    float ss = 0.f;
    #pragma unroll
    for (int i = 0; i < 8; i++) {
        v[i] = ((const float4*)src)[lane + 32 * i];
        ss += v[i].x * v[i].x + v[i].y * v[i].y + v[i].z * v[i].z + v[i].w * v[i].w;
    }
    #pragma unroll
    for (int o = 16; o; o >>= 1) ss += __shfl_xor_sync(0xffffffffu, ss, o);
    const float inv = 1.0f / fmaxf(sqrtf(ss), 1e-8f);

    #pragma unroll
    for (int i = 0; i < 8; i++) {
        __nv_bfloat162 h0 = __floats2bfloat162_rn(v[i].x * inv, v[i].y * inv);
        __nv_bfloat162 h1 = __floats2bfloat162_rn(v[i].z * inv, v[i].w * inv);
        uint2 packed;
        packed.x = *(uint32_t*)&h0;
        packed.y = *(uint32_t*)&h1;
        ((uint2*)dst)[lane + 32 * i] = packed;
    }
}

// ---------------------------------------------------------------------------
// Kernel 2: bf16 HMMA GEMM (mma.sync m16n8k16) + fused online logsumexp.
// 128x128 tile per CTA, 8 warps (2x4), BK=64, 3-stage cp.async pipeline in
// 96 KB dynamic smem, XOR-swizzled 128B rows. Epilogue reduces the 4 warp_n
// column-groups in smem -> ONE (m,s) partial per row per CTA, coalesced
// ct-major store.
// ---------------------------------------------------------------------------
__global__ __launch_bounds__(256, 2) void sim_lse_mma()
{
    extern __shared__ __align__(1024) uint8_t smem_dyn[];

    const int tid    = threadIdx.x;
    const int wid    = tid >> 5;
    const int lane   = tid & 31;
    const int warp_m = wid >> 2;        // 0..1
    const int warp_n = wid & 3;         // 0..3
    const int ct     = blockIdx.x;      // 0..63
    const int rb     = blockIdx.y;      // 0..31
    const int row0   = rb * BM;
    const int col0   = ct * BN;

    const uint32_t sbase = smem_u32(smem_dyn);

    // cp.async: 4 segments per matrix per chunk per thread.
    uint32_t doff[4];
    const __nv_bfloat16* gA[4];
    const __nv_bfloat16* gB[4];
    #pragma unroll
    for (int i = 0; i < 4; i++) {
        const int seg = tid + i * 256;
        const int r = seg >> 3;
        const int c = seg & 7;
        doff[i] = SWOFF128(r, c);
        gA[i] = &g_Xn[(size_t)(row0 + r) * D_DIM + c * 8];
        gB[i] = &g_Bn[(size_t)(col0 + r) * D_DIM + c * 8];
    }

    // ldmatrix row bases
    uint32_t a_row[4], b_row[4];
    uint32_t a_xr[4], b_xr[4];
    const uint32_t a_cb = lane >> 4;          // 0..1
    const uint32_t b_cb = (lane >> 3) & 1;    // 0..1
    #pragma unroll
    for (int mt = 0; mt < 4; mt++) {
        const int r = warp_m * 64 + mt * 16 + (lane & 15);
        a_row[mt] = (uint32_t)r << 7;
        a_xr[mt]  = (uint32_t)(r & 7);
    }
    #pragma unroll
    for (int nt = 0; nt < 4; nt++) {
        const int r = warp_n * 32 + nt * 8 + (lane & 7);
        b_row[nt] = (uint32_t)r << 7;
        b_xr[nt]  = (uint32_t)(r & 7);
    }

    float acc[4][4][4];
    #pragma unroll
    for (int mt = 0; mt < 4; mt++)
        #pragma unroll
        for (int nt = 0; nt < 4; nt++)
            #pragma unroll
            for (int q = 0; q < 4; q++) acc[mt][nt][q] = 0.f;

    // prologue: stages 0 and 1
    #pragma unroll
    for (int p = 0; p < 2; p++) {
        const int k0 = p * BK;
        const uint32_t dA = sbase + p * STAGE_BYTES;
        const uint32_t dB = dA + 128 * 128;
        #pragma unroll
        for (int i = 0; i < 4; i++) {
            CP_ASYNC16(dA + doff[i], gA[i] + k0);
            CP_ASYNC16(dB + doff[i], gB[i] + k0);
        }
        CP_COMMIT();
    }

    int stage = 0;
    for (int kc = 0; kc < NK; kc++) {
        CP_WAIT1();
        __syncthreads();

        if (kc + 2 < NK) {
            const int ps = (stage + 2 >= NSTAGE) ? stage + 2 - NSTAGE : stage + 2;
            const int k0 = (kc + 2) * BK;
            const uint32_t dA = sbase + ps * STAGE_BYTES;
            const uint32_t dB = dA + 128 * 128;
            #pragma unroll
            for (int i = 0; i < 4; i++) {
                CP_ASYNC16(dA + doff[i], gA[i] + k0);
                CP_ASYNC16(dB + doff[i], gB[i] + k0);
            }
        }
        CP_COMMIT();

        const uint32_t baseA = sbase + stage * STAGE_BYTES;
        const uint32_t baseB = baseA + 128 * 128;
        #pragma unroll
        for (int ks = 0; ks < 4; ks++) {
            uint32_t af[4][4], bf[4][2];
            #pragma unroll
            for (int mt = 0; mt < 4; mt++) {
                const uint32_t chunk = (2u * ks + a_cb) ^ a_xr[mt];
                LDSM_X4(af[mt], baseA + (a_row[mt] | (chunk << 4)));
            }
            #pragma unroll
            for (int nt = 0; nt < 4; nt++) {
                const uint32_t chunk = (2u * ks + b_cb) ^ b_xr[nt];
                LDSM_X2(bf[nt], baseB + (b_row[nt] | (chunk << 4)));
            }
            #pragma unroll
            for (int mt = 0; mt < 4; mt++)
                #pragma unroll
                for (int nt = 0; nt < 4; nt++)
                    MMA16816(acc[mt][nt], af[mt], bf[nt]);
        }
        stage = (stage + 1 >= NSTAGE) ? 0 : stage + 1;
    }

    // ---- Epilogue ----
    // Stage smem is idle after this barrier (last ldmatrix done everywhere).
    __syncthreads();
    float* sm_m = (float*)smem_dyn;            // [4][128]
    float* sm_s = (float*)smem_dyn + 4 * 128;  // [4][128]

    #pragma unroll
    for (int mt = 0; mt < 4; mt++) {
        #pragma unroll
        for (int h = 0; h < 2; h++) {
            const int rloc = warp_m * 64 + mt * 16 + (lane >> 2) + h * 8;
            const int gr = row0 + rloc;
            float v[8];
            float m = NEG_INF;
            #pragma unroll
            for (int nt = 0; nt < 4; nt++) {
                #pragma unroll
                for (int j = 0; j < 2; j++) {
                    float x = acc[mt][nt][h * 2 + j] * INV_TEMP;
                    const int gc = col0 + warp_n * 32 + nt * 8 + (lane & 3) * 2 + j;
                    if (gc == gr) g_diag[gr] = x;           // pos_sim diagonal
                    if (gc == N_ROWS + gr) x += 1.0f;       // hard-negative weight
                    v[nt * 2 + j] = x;
                    m = fmaxf(m, x);
                }
            }
            float s = 0.f;
            #pragma unroll
            for (int j = 0; j < 8; j++) s += __expf(v[j] - m);
            // combine across the 4 lanes of the quad (same row)
            #pragma unroll
            for (int off = 1; off <= 2; off <<= 1) {
                float om = __shfl_xor_sync(0xffffffffu, m, off);
                float os = __shfl_xor_sync(0xffffffffu, s, off);
                float mn = fmaxf(m, om);
                s = s * __expf(m - mn) + os * __expf(om - mn);
                m = mn;
            }
            if ((lane & 3) == 0) {
                sm_m[warp_n * 128 + rloc] = m;
                sm_s[warp_n * 128 + rloc] = s;
            }
        }
    }
    __syncthreads();

    // threads 0..127: combine 4 warp_n partials for one row; coalesced store.
    if (tid < 128) {
        float m = sm_m[tid];
        float s = sm_s[tid];
        #pragma unroll
        for (int j = 1; j < 4; j++) {
            float om = sm_m[j * 128 + tid];
            float os = sm_s[j * 128 + tid];
            float mn = fmaxf(m, om);
            s = s * __expf(m - mn) + os * __expf(om - mn);
            m = mn;
        }
        const size_t p = (size_t)ct * N_ROWS + row0 + tid;
        g_pm[p] = m;
        g_ps[p] = s;
    }
}

// ---------------------------------------------------------------------------
// Kernel 3a: thread-per-row combine of 64 ct-major partials -> lse - diag;
// block partial sum. Reads are coalesced (stride-1 across threads per c).
// ---------------------------------------------------------------------------
__global__ __launch_bounds__(256) void rowloss_kernel()
{
    const int tid = threadIdx.x;
    const int r = blockIdx.x * 256 + tid;

    float m = NEG_INF;
    #pragma unroll 8
    for (int c = 0; c < CT_TILES; c++)
        m = fmaxf(m, g_pm[(size_t)c * N_ROWS + r]);
    float s = 0.f;
    #pragma unroll 8
    for (int c = 0; c < CT_TILES; c++)
        s += g_ps[(size_t)c * N_ROWS + r] * __expf(g_pm[(size_t)c * N_ROWS + r] - m);
    float local = (m + logf(s)) - g_diag[r];

    #pragma unroll
    for (int o = 16; o; o >>= 1) local += __shfl_xor_sync(0xffffffffu, local, o);
    __shared__ float warp_sum[8];
    const int w = tid >> 5, l = tid & 31;
    if (l == 0) warp_sum[w] = local;
    __syncthreads();
    if (tid == 0) {
        float t = 0.f;
        #pragma unroll
        for (int i = 0; i < 8; i++) t += warp_sum[i];
        g_bsum[blockIdx.x] = t;
    }
}

// ---------------------------------------------------------------------------
// Kernel 3b: one warp sums the 16 block partials.
// ---------------------------------------------------------------------------
__global__ __launch_bounds__(32) void finalize_kernel(float* __restrict__ out)
{
    const int lane = threadIdx.x;
    float v = (lane < 16) ? g_bsum[lane] : 0.f;
    #pragma unroll
    for (int o = 16; o; o >>= 1) v += __shfl_xor_sync(0xffffffffu, v, o);
    if (lane == 0) out[0] = v / (float)N_ROWS;
}

// ---------------------------------------------------------------------------
extern "C" void kernel_launch(void* const* d_in, const int* in_sizes, int n_in,
                              void* d_out, int out_size)
{
    const float* inp = (const float*)d_in[0];
    const float* tgt = (const float*)d_in[1];
    const float* neg = (const float*)d_in[2];
    float* out = (float*)d_out;

    cudaFuncSetAttribute(sim_lse_mma,
                         cudaFuncAttributeMaxDynamicSharedMemorySize, SMEM_TOTAL);

    normalize_kernel<<<(3 * N_ROWS) / 8, 256>>>(inp, tgt, neg);

    dim3 grid(CT_TILES, RB_TILES);   // 64 x 32 = 2048 CTAs
    sim_lse_mma<<<grid, 256, SMEM_TOTAL>>>();

    rowloss_kernel<<<N_ROWS / 256, 256>>>();
    finalize_kernel<<<1, 32>>>(out);
}